// round 16
// baseline (speedup 1.0000x reference)
#include <cuda_runtime.h>
#include <cuda_fp16.h>
#include <math.h>
#include <stdint.h>

#define Bn   8
#define Cn   64
#define Hn   128
#define Wn   128
#define OUTn 128
#define Kn   9

// Scratch (device globals: allocation-free rule)
__device__ uint32_t g_xh  [Bn*Hn*Wn*32];   // x NHWC as packed fp16 pairs (16.8MB)
__device__ float    g_off [Bn*Hn*Wn*27];   // per-pixel {dy,dx,mask} x 9 taps
__device__ uint32_t g_wbhi[Kn*OUTn*32];    // w_conv fp16, [tap][o][kw pairs]
__device__ uint32_t g_obhi[Kn*32*32];      // offmask weights fp16-hi [tap][32][kw]
__device__ uint32_t g_oblo[Kn*32*32];      // offmask weights fp16-lo

// ---------------------------------------------------------------------------
__device__ __forceinline__ uint32_t smem_u32(const void* p) {
    uint32_t a;
    asm("{ .reg .u64 t; cvta.to.shared.u64 t, %1; cvt.u32.u64 %0, t; }"
        : "=r"(a) : "l"(p));
    return a;
}
__device__ __forceinline__ uint32_t pack_h2(float a, float b) {
    return (uint32_t)__half_as_ushort(__float2half_rn(a)) |
           ((uint32_t)__half_as_ushort(__float2half_rn(b)) << 16);
}
__device__ __forceinline__ void split2h(float v, float& hi, float& lo) {
    __half h = __float2half_rn(v);
    hi = __half2float(h);
    lo = v - hi;
}
__device__ __forceinline__ void mma16816(float* c, const uint32_t* a, const uint32_t* b) {
    asm volatile(
        "mma.sync.aligned.m16n8k16.row.col.f32.f16.f16.f32 "
        "{%0,%1,%2,%3}, {%4,%5,%6,%7}, {%8,%9}, {%0,%1,%2,%3};"
        : "+f"(c[0]), "+f"(c[1]), "+f"(c[2]), "+f"(c[3])
        : "r"(a[0]), "r"(a[1]), "r"(a[2]), "r"(a[3]), "r"(b[0]), "r"(b[1]));
}
__device__ __forceinline__ void ldmx4(uint32_t* r, uint32_t addr) {
    asm volatile(
        "ldmatrix.sync.aligned.m8n8.x4.shared.b16 {%0,%1,%2,%3}, [%4];"
        : "=r"(r[0]), "=r"(r[1]), "=r"(r[2]), "=r"(r[3]) : "r"(addr));
}

// ---------------------------------------------------------------------------
// Kernel 1: transpose x NCHW -> NHWC fp16 pairs
// ---------------------------------------------------------------------------
__global__ void xpose_kernel(const float* __restrict__ x) {
    __shared__ float t[64][33];
    int b = blockIdx.z, y = blockIdx.y, x0 = blockIdx.x * 32;
    int tx = threadIdx.x & 31, ty = threadIdx.x >> 5;
    #pragma unroll
    for (int i = 0; i < 8; i++) {
        int c = i * 8 + ty;
        t[c][tx] = x[((b * Cn + c) * Hn + y) * Wn + x0 + tx];
    }
    __syncthreads();
    int cp = threadIdx.x & 31, col2 = threadIdx.x >> 5;
    #pragma unroll
    for (int j = 0; j < 4; j++) {
        int col = col2 + j * 8;
        g_xh[(((b * Hn + y) * Wn + x0 + col) << 5) + cp] =
            pack_h2(t[2 * cp][col], t[2 * cp + 1][col]);
    }
}

// ---------------------------------------------------------------------------
// Kernel 2a: w_conv (OUT,C,3,3) -> fp16, layout [tap][o][kw pairs]
// ---------------------------------------------------------------------------
__global__ void wpose_kernel(const float* __restrict__ w_conv) {
    int i = blockIdx.x * 256 + threadIdx.x;
    if (i < Kn * OUTn * 32) {
        int tap = i >> 12, rem = i & 4095;
        int o = rem >> 5, kw = rem & 31;
        int c0 = kw * 2;
        float f0 = w_conv[o * 576 + c0 * 9 + tap];
        float f1 = w_conv[o * 576 + (c0 + 1) * 9 + tap];
        g_wbhi[i] = pack_h2(f0, f1);
    }
}

// ---------------------------------------------------------------------------
// Kernel 2b: pack offset(18)+mask(9) weights fp16 hi/lo, [tap][32 padded][kw]
// ---------------------------------------------------------------------------
__global__ void wpose2_kernel(const float* __restrict__ w_off,
                              const float* __restrict__ w_mask) {
    int i = blockIdx.x * 256 + threadIdx.x;
    if (i < Kn * 32 * 32) {
        int tap = i >> 10, rem = i & 1023;
        int o = rem >> 5, kw = rem & 31;
        int c0 = kw * 2;
        float f0 = 0.f, f1 = 0.f;
        if (o < 18) {
            f0 = w_off[o * 576 + c0 * 9 + tap];
            f1 = w_off[o * 576 + (c0 + 1) * 9 + tap];
        } else if (o < 27) {
            f0 = w_mask[(o - 18) * 576 + c0 * 9 + tap];
            f1 = w_mask[(o - 18) * 576 + (c0 + 1) * 9 + tap];
        }
        float h0, l0, h1, l1;
        split2h(f0, h0, l0);
        split2h(f1, h1, l1);
        g_obhi[i] = pack_h2(h0, h1);
        g_oblo[i] = pack_h2(l0, l1);
    }
}

// ---------------------------------------------------------------------------
// Kernel 3: tensor-core offset+mask conv (R8 2-row version; fill reads g_xh).
// ---------------------------------------------------------------------------
#define RS2H   72
#define SM2_XS  0
#define SM2_BHI 74880
#define SM2_BLO 84096
#define SM2_BSH 93312
#define SM2_TOT 93440
#define RS     36
#define SD2    33

__global__ void __launch_bounds__(256, 2)
offmask_kernel(const float* __restrict__ b_off,
               const float* __restrict__ b_mask) {
    extern __shared__ __align__(16) char smc[];
    uint32_t sb = smem_u32(smc);
    int tid = threadIdx.x, wid = tid >> 5, lid = tid & 31;
    int h2 = blockIdx.x, b = blockIdx.y;
    int h0 = h2 * 2;

    int warp_m = wid >> 1, warp_n = wid & 1;
    int fr = lid >> 2, fc = lid & 3;

    uint32_t a_row_l = ((uint32_t)(lid >> 3) & 1) * 8 + (lid & 7);
    uint32_t a_col_l = ((uint32_t)(lid >> 4)) * 16;
    uint32_t b_row_l = ((uint32_t)(lid >> 4)) * 8 + (lid & 7);
    uint32_t b_col_l = ((uint32_t)(lid >> 3) & 1) * 16;

    if (tid < 27) ((float*)(smc + SM2_BSH))[tid] =
        (tid < 18) ? b_off[tid] : b_mask[tid - 18];

    for (int i = tid; i < 4 * 130 * 16; i += 256) {
        int rr = i / (130 * 16), rem = i - rr * 130 * 16;
        int pxi = rem >> 4, ch4 = rem & 15;
        int y = h0 - 1 + rr, cx = pxi - 1;
        uint2 val = make_uint2(0u, 0u);
        if (y >= 0 && y < Hn && cx >= 0 && cx < Wn)
            val = *(const uint2*)(g_xh + (((b * Hn + y) * Wn + cx) << 5) + ch4 * 2);
        *(uint2*)(smc + SM2_XS + ((rr * 130 + pxi) * RS2H + ch4 * 4) * 2) = val;
    }

    float acc[4][2][4];
    #pragma unroll
    for (int i = 0; i < 4; i++)
        #pragma unroll
        for (int j = 0; j < 2; j++)
            #pragma unroll
            for (int q = 0; q < 4; q++) acc[i][j][q] = 0.f;

    for (int k = 0; k < Kn; k++) {
        int ky = k / 3, kx = k - ky * 3;
        __syncthreads();
        if (tid < 128) {
            int is_lo = tid >> 6, j = tid & 63;
            int o = j >> 1, kw0 = (j & 1) * 16;
            const uint4* src = (const uint4*)(
                (is_lo ? g_oblo : g_obhi) + (k << 10) + o * 32 + kw0);
            char* dst = smc + (is_lo ? SM2_BLO : SM2_BHI);
            uint32_t wbase = (uint32_t)(o * RS + kw0);
            #pragma unroll
            for (int t = 0; t < 4; t++)
                *(uint4*)(dst + (wbase + t * 4) * 4) = src[t];
        }
        __syncthreads();

        uint32_t abase0 = (uint32_t)((ky * 130 + kx) * (RS2H * 2));
        #pragma unroll
        for (int s = 0; s < 4; s++) {
            uint32_t bh[2][2], bl[2][2];
            {
                uint32_t boff = ((uint32_t)(warp_n * 16) + b_row_l) * (RS * 4)
                              + (uint32_t)s * 32 + b_col_l;
                uint32_t t0[4], t1[4];
                ldmx4(t0, sb + SM2_BHI + boff);
                ldmx4(t1, sb + SM2_BLO + boff);
                bh[0][0] = t0[0]; bh[0][1] = t0[1];
                bh[1][0] = t0[2]; bh[1][1] = t0[3];
                bl[0][0] = t1[0]; bl[0][1] = t1[1];
                bl[1][0] = t1[2]; bl[1][1] = t1[3];
            }
            #pragma unroll
            for (int mi = 0; mi < 4; mi++) {
                int mbase = warp_m * 64 + mi * 16;
                int rrow = (mbase >> 7);
                int pxb  = mbase & 127;
                uint32_t aoff = abase0 + (uint32_t)(rrow * 130 + pxb) * (RS2H * 2)
                              + a_row_l * (RS2H * 2) + (uint32_t)s * 32 + a_col_l;
                uint32_t ah[4];
                ldmx4(ah, sb + SM2_XS + aoff);
                #pragma unroll
                for (int ni = 0; ni < 2; ni++) {
                    mma16816(acc[mi][ni], ah, bh[ni]);
                    mma16816(acc[mi][ni], ah, bl[ni]);
                }
            }
        }
    }

    __syncthreads();
    float* stg = (float*)smc;
    #pragma unroll
    for (int mi = 0; mi < 4; mi++) {
        int pr = warp_m * 64 + mi * 16 + fr;
        #pragma unroll
        for (int ni = 0; ni < 2; ni++) {
            int oc = warp_n * 16 + ni * 8 + fc * 2;
            stg[pr * SD2 + oc]           = acc[mi][ni][0];
            stg[pr * SD2 + oc + 1]       = acc[mi][ni][1];
            stg[(pr + 8) * SD2 + oc]     = acc[mi][ni][2];
            stg[(pr + 8) * SD2 + oc + 1] = acc[mi][ni][3];
        }
    }
    __syncthreads();

    {
        const float* bsh = (const float*)(smc + SM2_BSH);
        int r = tid >> 7, w = tid & 127;
        int h = h0 + r;
        const float* row = stg + tid * SD2;
        float* op = g_off + ((b * Hn + h) * Wn + w) * 27;
        #pragma unroll
        for (int k = 0; k < Kn; k++) {
            op[k * 3 + 0] = row[2 * k]     + bsh[2 * k];
            op[k * 3 + 1] = row[2 * k + 1] + bsh[2 * k + 1];
            float t = row[18 + k] + bsh[18 + k];
            op[k * 3 + 2] = 1.f / (1.f + expf(-t));
        }
    }
}

// ---------------------------------------------------------------------------
// Kernel 4: fused bilinear sample + fp16 mma.sync GEMM (R14 path), now at
// 3 CTAs/SM: full 128x128 tile, 73.7KB smem x3 = 221KB <= 228KB.
// ---------------------------------------------------------------------------
#define SM_A0   0
#define SM_A1   18432
#define SM_B0   36864
#define SM_B1   55296
#define SM_MAIN 73728
#define SD    132

__global__ void __launch_bounds__(256, 3)
main_kernel(float* __restrict__ out) {
    extern __shared__ __align__(16) char smc[];
    uint32_t sb = smem_u32(smc);
    int tid = threadIdx.x, wid = tid >> 5, lid = tid & 31;
    int h = blockIdx.x, b = blockIdx.y;

    int warp_m = wid & 1, warp_n = wid >> 1;
    int fr = lid >> 2, fc = lid & 3;
    int hwb = (b * Hn + h) * Wn;

    int ppx   = lid >> 4;
    int chunk = lid & 15;

    uint32_t a_row_l = ((uint32_t)(lid >> 3) & 1) * 8 + (lid & 7);
    uint32_t a_col_l = ((uint32_t)(lid >> 4)) * 16;
    uint32_t b_row_l = ((uint32_t)(lid >> 4)) * 8 + (lid & 7);
    uint32_t b_col_l = ((uint32_t)(lid >> 3) & 1) * 16;

    auto do_sample = [&](int k, char* abuf) {
        int ky = k / 3, kx = k - ky * 3;
        #pragma unroll 4
        for (int pass = 0; pass < 8; pass++) {
            int px = wid * 16 + pass * 2 + ppx;
            const float* op = g_off + (hwb + px) * 27 + k * 3;
            float dy = op[0], dx = op[1], m = op[2];
            float gy = (float)(h - 1 + ky) + dy;
            float gx = (float)(px - 1 + kx) + dx;
            float y0f = floorf(gy), x0f = floorf(gx);
            float wy = gy - y0f, wx = gx - x0f;
            int y0 = (int)y0f, x0i = (int)x0f;

            float s0 = 0.f, s1 = 0.f, s2 = 0.f, s3 = 0.f;
            #pragma unroll
            for (int cor = 0; cor < 4; cor++) {
                int yi = y0 + (cor >> 1), xi = x0i + (cor & 1);
                float wgt = ((cor >> 1) ? wy : 1.f - wy) *
                            ((cor & 1)  ? wx : 1.f - wx) * m;
                if (yi < 0 || yi >= Hn || xi < 0 || xi >= Wn) wgt = 0.f;
                int yc = min(max(yi, 0), Hn - 1);
                int xc = min(max(xi, 0), Wn - 1);
                uint2 v = *(const uint2*)(
                    g_xh + (((b * Hn + yc) * Wn + xc) << 5) + chunk * 2);
                float2 f0 = __half22float2(*(__half2*)&v.x);
                float2 f1 = __half22float2(*(__half2*)&v.y);
                s0 += wgt * f0.x; s1 += wgt * f0.y;
                s2 += wgt * f1.x; s3 += wgt * f1.y;
            }
            uint32_t wbase = (uint32_t)(px * RS + chunk * 2);
            *(uint2*)(abuf + wbase * 4) =
                make_uint2(pack_h2(s0, s1), pack_h2(s2, s3));
        }
    };

    auto do_loadB = [&](int k, char* bbuf) {
        int o = tid >> 1, kw0 = (tid & 1) * 16;
        const uint4* shi = (const uint4*)(g_wbhi + (k << 12) + o * 32 + kw0);
        uint32_t wbase = (uint32_t)(o * RS + kw0);
        #pragma unroll
        for (int t = 0; t < 4; t++)
            *(uint4*)(bbuf + (wbase + t * 4) * 4) = shi[t];
    };

    float acc[4][4][4];
    #pragma unroll
    for (int i = 0; i < 4; i++)
        #pragma unroll
        for (int j = 0; j < 4; j++)
            #pragma unroll
            for (int q = 0; q < 4; q++) acc[i][j][q] = 0.f;

    do_sample(0, smc + SM_A0);
    do_loadB(0, smc + SM_B0);

    for (int k = 0; k < Kn; k++) {
        __syncthreads();
        if (k + 1 < Kn) {
            char* abuf = smc + (((k + 1) & 1) ? SM_A1 : SM_A0);
            char* bbuf = smc + (((k + 1) & 1) ? SM_B1 : SM_B0);
            do_sample(k + 1, abuf);
            do_loadB(k + 1, bbuf);
        }

        uint32_t abase = (k & 1) ? SM_A1 : SM_A0;
        uint32_t bbase = (k & 1) ? SM_B1 : SM_B0;
        #pragma unroll
        for (int s = 0; s < 4; s++) {
            uint32_t bh[4][2];
            #pragma unroll
            for (int ni2 = 0; ni2 < 2; ni2++) {
                uint32_t brow = (uint32_t)(warp_n * 32 + ni2 * 16) + b_row_l;
                uint32_t boff = brow * (RS * 4) + (uint32_t)s * 32 + b_col_l;
                uint32_t t0[4];
                ldmx4(t0, sb + bbase + boff);
                bh[2*ni2][0] = t0[0]; bh[2*ni2][1] = t0[1];
                bh[2*ni2+1][0] = t0[2]; bh[2*ni2+1][1] = t0[3];
            }
            #pragma unroll
            for (int mi = 0; mi < 4; mi++) {
                uint32_t arow = (uint32_t)(warp_m * 64 + mi * 16) + a_row_l;
                uint32_t aoff = arow * (RS * 4) + (uint32_t)s * 32 + a_col_l;
                uint32_t ah[4];
                ldmx4(ah, sb + abase + aoff);
                #pragma unroll
                for (int ni = 0; ni < 4; ni++)
                    mma16816(acc[mi][ni], ah, bh[ni]);
            }
        }
    }

    __syncthreads();
    float* stg = (float*)smc;
    #pragma unroll
    for (int mi = 0; mi < 4; mi++) {
        int pr = warp_m * 64 + mi * 16 + fr;
        #pragma unroll
        for (int ni = 0; ni < 4; ni++) {
            int oc = warp_n * 32 + ni * 8 + fc * 2;
            stg[oc * SD + pr]           = acc[mi][ni][0];
            stg[(oc + 1) * SD + pr]     = acc[mi][ni][1];
            stg[oc * SD + pr + 8]       = acc[mi][ni][2];
            stg[(oc + 1) * SD + pr + 8] = acc[mi][ni][3];
        }
    }
    __syncthreads();

    #pragma unroll
    for (int t = 0; t < 16; t++) {
        int i4 = tid + t * 256;
        int o = i4 >> 5, p4 = (i4 & 31) * 4;
        float4 v = *(float4*)(stg + o * SD + p4);
        *(float4*)(out + ((size_t)(b * OUTn + o) * Hn + h) * Wn + p4) = v;
    }
}

// ---------------------------------------------------------------------------
extern "C" void kernel_launch(void* const* d_in, const int* in_sizes, int n_in,
                              void* d_out, int out_size) {
    const float* x      = (const float*)d_in[0];
    const float* w_off  = (const float*)d_in[1];
    const float* b_off  = (const float*)d_in[2];
    const float* w_mask = (const float*)d_in[3];
    const float* b_mask = (const float*)d_in[4];
    const float* w_conv = (const float*)d_in[5];
    float* out = (float*)d_out;

    cudaFuncSetAttribute(offmask_kernel,
                         cudaFuncAttributeMaxDynamicSharedMemorySize, SM2_TOT);
    cudaFuncSetAttribute(main_kernel,
                         cudaFuncAttributeMaxDynamicSharedMemorySize, SM_MAIN);

    xpose_kernel<<<dim3(4, 128, 8), 256>>>(x);
    wpose_kernel<<<dim3((Kn * OUTn * 32 + 255) / 256), 256>>>(w_conv);
    wpose2_kernel<<<dim3((Kn * 32 * 32 + 255) / 256), 256>>>(w_off, w_mask);

    offmask_kernel<<<dim3(Hn / 2, Bn), 256, SM2_TOT>>>(b_off, b_mask);

    main_kernel<<<dim3(Hn, Bn), 256, SM_MAIN>>>(out);
}

// round 17
// speedup vs baseline: 1.2477x; 1.2477x over previous
#include <cuda_runtime.h>
#include <cuda_fp16.h>
#include <math.h>
#include <stdint.h>

#define Bn   8
#define Cn   64
#define Hn   128
#define Wn   128
#define OUTn 128
#define Kn   9

// Scratch (device globals: allocation-free rule)
__device__ uint32_t g_xh  [Bn*Hn*Wn*32];   // x NHWC as packed fp16 pairs (16.8MB)
__device__ float    g_off [Bn*Hn*Wn*27];   // per-pixel {dy,dx,mask} x 9 taps
__device__ uint32_t g_wbhi[Kn*OUTn*32];    // w_conv fp16, [tap][o][kw pairs]
__device__ uint32_t g_obhi[Kn*32*32];      // offmask weights fp16-hi [tap][32][kw]
__device__ uint32_t g_oblo[Kn*32*32];      // offmask weights fp16-lo

// ---------------------------------------------------------------------------
__device__ __forceinline__ uint32_t smem_u32(const void* p) {
    uint32_t a;
    asm("{ .reg .u64 t; cvta.to.shared.u64 t, %1; cvt.u32.u64 %0, t; }"
        : "=r"(a) : "l"(p));
    return a;
}
__device__ __forceinline__ uint32_t pack_h2(float a, float b) {
    return (uint32_t)__half_as_ushort(__float2half_rn(a)) |
           ((uint32_t)__half_as_ushort(__float2half_rn(b)) << 16);
}
__device__ __forceinline__ void split2h(float v, float& hi, float& lo) {
    __half h = __float2half_rn(v);
    hi = __half2float(h);
    lo = v - hi;
}
__device__ __forceinline__ void mma16816(float* c, const uint32_t* a, const uint32_t* b) {
    asm volatile(
        "mma.sync.aligned.m16n8k16.row.col.f32.f16.f16.f32 "
        "{%0,%1,%2,%3}, {%4,%5,%6,%7}, {%8,%9}, {%0,%1,%2,%3};"
        : "+f"(c[0]), "+f"(c[1]), "+f"(c[2]), "+f"(c[3])
        : "r"(a[0]), "r"(a[1]), "r"(a[2]), "r"(a[3]), "r"(b[0]), "r"(b[1]));
}
__device__ __forceinline__ void ldmx4(uint32_t* r, uint32_t addr) {
    asm volatile(
        "ldmatrix.sync.aligned.m8n8.x4.shared.b16 {%0,%1,%2,%3}, [%4];"
        : "=r"(r[0]), "=r"(r[1]), "=r"(r[2]), "=r"(r[3]) : "r"(addr));
}

// ---------------------------------------------------------------------------
// Kernel 1: transpose x NCHW -> NHWC fp16 pairs
// ---------------------------------------------------------------------------
__global__ void xpose_kernel(const float* __restrict__ x) {
    __shared__ float t[64][33];
    int b = blockIdx.z, y = blockIdx.y, x0 = blockIdx.x * 32;
    int tx = threadIdx.x & 31, ty = threadIdx.x >> 5;
    #pragma unroll
    for (int i = 0; i < 8; i++) {
        int c = i * 8 + ty;
        t[c][tx] = x[((b * Cn + c) * Hn + y) * Wn + x0 + tx];
    }
    __syncthreads();
    int cp = threadIdx.x & 31, col2 = threadIdx.x >> 5;
    #pragma unroll
    for (int j = 0; j < 4; j++) {
        int col = col2 + j * 8;
        g_xh[(((b * Hn + y) * Wn + x0 + col) << 5) + cp] =
            pack_h2(t[2 * cp][col], t[2 * cp + 1][col]);
    }
}

// ---------------------------------------------------------------------------
// Kernel 2a: w_conv (OUT,C,3,3) -> fp16, layout [tap][o][kw pairs]
// ---------------------------------------------------------------------------
__global__ void wpose_kernel(const float* __restrict__ w_conv) {
    int i = blockIdx.x * 256 + threadIdx.x;
    if (i < Kn * OUTn * 32) {
        int tap = i >> 12, rem = i & 4095;
        int o = rem >> 5, kw = rem & 31;
        int c0 = kw * 2;
        float f0 = w_conv[o * 576 + c0 * 9 + tap];
        float f1 = w_conv[o * 576 + (c0 + 1) * 9 + tap];
        g_wbhi[i] = pack_h2(f0, f1);
    }
}

// ---------------------------------------------------------------------------
// Kernel 2b: pack offset(18)+mask(9) weights fp16 hi/lo, [tap][32 padded][kw]
// ---------------------------------------------------------------------------
__global__ void wpose2_kernel(const float* __restrict__ w_off,
                              const float* __restrict__ w_mask) {
    int i = blockIdx.x * 256 + threadIdx.x;
    if (i < Kn * 32 * 32) {
        int tap = i >> 10, rem = i & 1023;
        int o = rem >> 5, kw = rem & 31;
        int c0 = kw * 2;
        float f0 = 0.f, f1 = 0.f;
        if (o < 18) {
            f0 = w_off[o * 576 + c0 * 9 + tap];
            f1 = w_off[o * 576 + (c0 + 1) * 9 + tap];
        } else if (o < 27) {
            f0 = w_mask[(o - 18) * 576 + c0 * 9 + tap];
            f1 = w_mask[(o - 18) * 576 + (c0 + 1) * 9 + tap];
        }
        float h0, l0, h1, l1;
        split2h(f0, h0, l0);
        split2h(f1, h1, l1);
        g_obhi[i] = pack_h2(h0, h1);
        g_oblo[i] = pack_h2(l0, l1);
    }
}

// ---------------------------------------------------------------------------
// Kernel 3: tensor-core offset+mask conv (R8 2-row version; fill reads g_xh).
// ---------------------------------------------------------------------------
#define RS2H   72
#define SM2_XS  0
#define SM2_BHI 74880
#define SM2_BLO 84096
#define SM2_BSH 93312
#define SM2_TOT 93440
#define RS     36
#define SD2    33

__global__ void __launch_bounds__(256, 2)
offmask_kernel(const float* __restrict__ b_off,
               const float* __restrict__ b_mask) {
    extern __shared__ __align__(16) char smc[];
    uint32_t sb = smem_u32(smc);
    int tid = threadIdx.x, wid = tid >> 5, lid = tid & 31;
    int h2 = blockIdx.x, b = blockIdx.y;
    int h0 = h2 * 2;

    int warp_m = wid >> 1, warp_n = wid & 1;
    int fr = lid >> 2, fc = lid & 3;

    uint32_t a_row_l = ((uint32_t)(lid >> 3) & 1) * 8 + (lid & 7);
    uint32_t a_col_l = ((uint32_t)(lid >> 4)) * 16;
    uint32_t b_row_l = ((uint32_t)(lid >> 4)) * 8 + (lid & 7);
    uint32_t b_col_l = ((uint32_t)(lid >> 3) & 1) * 16;

    if (tid < 27) ((float*)(smc + SM2_BSH))[tid] =
        (tid < 18) ? b_off[tid] : b_mask[tid - 18];

    for (int i = tid; i < 4 * 130 * 16; i += 256) {
        int rr = i / (130 * 16), rem = i - rr * 130 * 16;
        int pxi = rem >> 4, ch4 = rem & 15;
        int y = h0 - 1 + rr, cx = pxi - 1;
        uint2 val = make_uint2(0u, 0u);
        if (y >= 0 && y < Hn && cx >= 0 && cx < Wn)
            val = *(const uint2*)(g_xh + (((b * Hn + y) * Wn + cx) << 5) + ch4 * 2);
        *(uint2*)(smc + SM2_XS + ((rr * 130 + pxi) * RS2H + ch4 * 4) * 2) = val;
    }

    float acc[4][2][4];
    #pragma unroll
    for (int i = 0; i < 4; i++)
        #pragma unroll
        for (int j = 0; j < 2; j++)
            #pragma unroll
            for (int q = 0; q < 4; q++) acc[i][j][q] = 0.f;

    for (int k = 0; k < Kn; k++) {
        int ky = k / 3, kx = k - ky * 3;
        __syncthreads();
        if (tid < 128) {
            int is_lo = tid >> 6, j = tid & 63;
            int o = j >> 1, kw0 = (j & 1) * 16;
            const uint4* src = (const uint4*)(
                (is_lo ? g_oblo : g_obhi) + (k << 10) + o * 32 + kw0);
            char* dst = smc + (is_lo ? SM2_BLO : SM2_BHI);
            uint32_t wbase = (uint32_t)(o * RS + kw0);
            #pragma unroll
            for (int t = 0; t < 4; t++)
                *(uint4*)(dst + (wbase + t * 4) * 4) = src[t];
        }
        __syncthreads();

        uint32_t abase0 = (uint32_t)((ky * 130 + kx) * (RS2H * 2));
        #pragma unroll
        for (int s = 0; s < 4; s++) {
            uint32_t bh[2][2], bl[2][2];
            {
                uint32_t boff = ((uint32_t)(warp_n * 16) + b_row_l) * (RS * 4)
                              + (uint32_t)s * 32 + b_col_l;
                uint32_t t0[4], t1[4];
                ldmx4(t0, sb + SM2_BHI + boff);
                ldmx4(t1, sb + SM2_BLO + boff);
                bh[0][0] = t0[0]; bh[0][1] = t0[1];
                bh[1][0] = t0[2]; bh[1][1] = t0[3];
                bl[0][0] = t1[0]; bl[0][1] = t1[1];
                bl[1][0] = t1[2]; bl[1][1] = t1[3];
            }
            #pragma unroll
            for (int mi = 0; mi < 4; mi++) {
                int mbase = warp_m * 64 + mi * 16;
                int rrow = (mbase >> 7);
                int pxb  = mbase & 127;
                uint32_t aoff = abase0 + (uint32_t)(rrow * 130 + pxb) * (RS2H * 2)
                              + a_row_l * (RS2H * 2) + (uint32_t)s * 32 + a_col_l;
                uint32_t ah[4];
                ldmx4(ah, sb + SM2_XS + aoff);
                #pragma unroll
                for (int ni = 0; ni < 2; ni++) {
                    mma16816(acc[mi][ni], ah, bh[ni]);
                    mma16816(acc[mi][ni], ah, bl[ni]);
                }
            }
        }
    }

    __syncthreads();
    float* stg = (float*)smc;
    #pragma unroll
    for (int mi = 0; mi < 4; mi++) {
        int pr = warp_m * 64 + mi * 16 + fr;
        #pragma unroll
        for (int ni = 0; ni < 2; ni++) {
            int oc = warp_n * 16 + ni * 8 + fc * 2;
            stg[pr * SD2 + oc]           = acc[mi][ni][0];
            stg[pr * SD2 + oc + 1]       = acc[mi][ni][1];
            stg[(pr + 8) * SD2 + oc]     = acc[mi][ni][2];
            stg[(pr + 8) * SD2 + oc + 1] = acc[mi][ni][3];
        }
    }
    __syncthreads();

    {
        const float* bsh = (const float*)(smc + SM2_BSH);
        int r = tid >> 7, w = tid & 127;
        int h = h0 + r;
        const float* row = stg + tid * SD2;
        float* op = g_off + ((b * Hn + h) * Wn + w) * 27;
        #pragma unroll
        for (int k = 0; k < Kn; k++) {
            op[k * 3 + 0] = row[2 * k]     + bsh[2 * k];
            op[k * 3 + 1] = row[2 * k + 1] + bsh[2 * k + 1];
            float t = row[18 + k] + bsh[18 + k];
            op[k * 3 + 2] = 1.f / (1.f + expf(-t));
        }
    }
}

// ---------------------------------------------------------------------------
// Kernel 4: fused bilinear sample + fp16 mma.sync GEMM (R14: fp16 gather,
// single-B fp16, double-buffered, 2 CTAs/SM, 128 regs).
// ---------------------------------------------------------------------------
#define SM_A0   0
#define SM_A1   18432
#define SM_B0   36864
#define SM_B1   55296
#define SM_MAIN 73728
#define SD    132

__global__ void __launch_bounds__(256, 2)
main_kernel(float* __restrict__ out) {
    extern __shared__ __align__(16) char smc[];
    uint32_t sb = smem_u32(smc);
    int tid = threadIdx.x, wid = tid >> 5, lid = tid & 31;
    int h = blockIdx.x, b = blockIdx.y;

    int warp_m = wid & 1, warp_n = wid >> 1;
    int fr = lid >> 2, fc = lid & 3;
    int hwb = (b * Hn + h) * Wn;

    int ppx   = lid >> 4;
    int chunk = lid & 15;

    uint32_t a_row_l = ((uint32_t)(lid >> 3) & 1) * 8 + (lid & 7);
    uint32_t a_col_l = ((uint32_t)(lid >> 4)) * 16;
    uint32_t b_row_l = ((uint32_t)(lid >> 4)) * 8 + (lid & 7);
    uint32_t b_col_l = ((uint32_t)(lid >> 3) & 1) * 16;

    auto do_sample = [&](int k, char* abuf) {
        int ky = k / 3, kx = k - ky * 3;
        #pragma unroll 4
        for (int pass = 0; pass < 8; pass++) {
            int px = wid * 16 + pass * 2 + ppx;
            const float* op = g_off + (hwb + px) * 27 + k * 3;
            float dy = op[0], dx = op[1], m = op[2];
            float gy = (float)(h - 1 + ky) + dy;
            float gx = (float)(px - 1 + kx) + dx;
            float y0f = floorf(gy), x0f = floorf(gx);
            float wy = gy - y0f, wx = gx - x0f;
            int y0 = (int)y0f, x0i = (int)x0f;

            float s0 = 0.f, s1 = 0.f, s2 = 0.f, s3 = 0.f;
            #pragma unroll
            for (int cor = 0; cor < 4; cor++) {
                int yi = y0 + (cor >> 1), xi = x0i + (cor & 1);
                float wgt = ((cor >> 1) ? wy : 1.f - wy) *
                            ((cor & 1)  ? wx : 1.f - wx) * m;
                if (yi < 0 || yi >= Hn || xi < 0 || xi >= Wn) wgt = 0.f;
                int yc = min(max(yi, 0), Hn - 1);
                int xc = min(max(xi, 0), Wn - 1);
                uint2 v = *(const uint2*)(
                    g_xh + (((b * Hn + yc) * Wn + xc) << 5) + chunk * 2);
                float2 f0 = __half22float2(*(__half2*)&v.x);
                float2 f1 = __half22float2(*(__half2*)&v.y);
                s0 += wgt * f0.x; s1 += wgt * f0.y;
                s2 += wgt * f1.x; s3 += wgt * f1.y;
            }
            uint32_t wbase = (uint32_t)(px * RS + chunk * 2);
            *(uint2*)(abuf + wbase * 4) =
                make_uint2(pack_h2(s0, s1), pack_h2(s2, s3));
        }
    };

    auto do_loadB = [&](int k, char* bbuf) {
        int o = tid >> 1, kw0 = (tid & 1) * 16;
        const uint4* shi = (const uint4*)(g_wbhi + (k << 12) + o * 32 + kw0);
        uint32_t wbase = (uint32_t)(o * RS + kw0);
        #pragma unroll
        for (int t = 0; t < 4; t++)
            *(uint4*)(bbuf + (wbase + t * 4) * 4) = shi[t];
    };

    float acc[4][4][4];
    #pragma unroll
    for (int i = 0; i < 4; i++)
        #pragma unroll
        for (int j = 0; j < 4; j++)
            #pragma unroll
            for (int q = 0; q < 4; q++) acc[i][j][q] = 0.f;

    do_sample(0, smc + SM_A0);
    do_loadB(0, smc + SM_B0);

    for (int k = 0; k < Kn; k++) {
        __syncthreads();
        if (k + 1 < Kn) {
            char* abuf = smc + (((k + 1) & 1) ? SM_A1 : SM_A0);
            char* bbuf = smc + (((k + 1) & 1) ? SM_B1 : SM_B0);
            do_sample(k + 1, abuf);
            do_loadB(k + 1, bbuf);
        }

        uint32_t abase = (k & 1) ? SM_A1 : SM_A0;
        uint32_t bbase = (k & 1) ? SM_B1 : SM_B0;
        #pragma unroll
        for (int s = 0; s < 4; s++) {
            uint32_t bh[4][2];
            #pragma unroll
            for (int ni2 = 0; ni2 < 2; ni2++) {
                uint32_t brow = (uint32_t)(warp_n * 32 + ni2 * 16) + b_row_l;
                uint32_t boff = brow * (RS * 4) + (uint32_t)s * 32 + b_col_l;
                uint32_t t0[4];
                ldmx4(t0, sb + bbase + boff);
                bh[2*ni2][0] = t0[0]; bh[2*ni2][1] = t0[1];
                bh[2*ni2+1][0] = t0[2]; bh[2*ni2+1][1] = t0[3];
            }
            #pragma unroll
            for (int mi = 0; mi < 4; mi++) {
                uint32_t arow = (uint32_t)(warp_m * 64 + mi * 16) + a_row_l;
                uint32_t aoff = arow * (RS * 4) + (uint32_t)s * 32 + a_col_l;
                uint32_t ah[4];
                ldmx4(ah, sb + abase + aoff);
                #pragma unroll
                for (int ni = 0; ni < 4; ni++)
                    mma16816(acc[mi][ni], ah, bh[ni]);
            }
        }
    }

    __syncthreads();
    float* stg = (float*)smc;
    #pragma unroll
    for (int mi = 0; mi < 4; mi++) {
        int pr = warp_m * 64 + mi * 16 + fr;
        #pragma unroll
        for (int ni = 0; ni < 4; ni++) {
            int oc = warp_n * 32 + ni * 8 + fc * 2;
            stg[oc * SD + pr]           = acc[mi][ni][0];
            stg[(oc + 1) * SD + pr]     = acc[mi][ni][1];
            stg[oc * SD + pr + 8]       = acc[mi][ni][2];
            stg[(oc + 1) * SD + pr + 8] = acc[mi][ni][3];
        }
    }
    __syncthreads();

    #pragma unroll
    for (int t = 0; t < 16; t++) {
        int i4 = tid + t * 256;
        int o = i4 >> 5, p4 = (i4 & 31) * 4;
        float4 v = *(float4*)(stg + o * SD + p4);
        *(float4*)(out + ((size_t)(b * OUTn + o) * Hn + h) * Wn + p4) = v;
    }
}

// ---------------------------------------------------------------------------
extern "C" void kernel_launch(void* const* d_in, const int* in_sizes, int n_in,
                              void* d_out, int out_size) {
    const float* x      = (const float*)d_in[0];
    const float* w_off  = (const float*)d_in[1];
    const float* b_off  = (const float*)d_in[2];
    const float* w_mask = (const float*)d_in[3];
    const float* b_mask = (const float*)d_in[4];
    const float* w_conv = (const float*)d_in[5];
    float* out = (float*)d_out;

    cudaFuncSetAttribute(offmask_kernel,
                         cudaFuncAttributeMaxDynamicSharedMemorySize, SM2_TOT);
    cudaFuncSetAttribute(main_kernel,
                         cudaFuncAttributeMaxDynamicSharedMemorySize, SM_MAIN);

    xpose_kernel<<<dim3(4, 128, 8), 256>>>(x);
    wpose_kernel<<<dim3((Kn * OUTn * 32 + 255) / 256), 256>>>(w_conv);
    wpose2_kernel<<<dim3((Kn * 32 * 32 + 255) / 256), 256>>>(w_off, w_mask);

    offmask_kernel<<<dim3(Hn / 2, Bn), 256, SM2_TOT>>>(b_off, b_mask);

    main_kernel<<<dim3(Hn, Bn), 256, SM_MAIN>>>(out);
}